// round 3
// baseline (speedup 1.0000x reference)
#include <cuda_runtime.h>
#include <cstddef>

// Problem constants
#define N_NODES 50000
#define N_PAD   50048        // padded row count so stage2 loads need no guards
#define KNBR    32
#define FDIM    128
#define EDIM    8
#define KDIM    1024         // = FDIM * EDIM  (flattened contraction dim)

// Scratch: G[i, n*128+l]  (padded rows are never stored to output)
__device__ float g_scratch[N_PAD * KDIM];      // ~205 MB static device global
// Rearranged weights: Wr[n*128+l, m] = w[l, m, n]
__device__ float w_r[KDIM * FDIM];             // 512 KB
// nlist dtype flag: 1 = int64 storage, 0 = int32 storage
__device__ int g_nlist_is64;

// ---------------------------------------------------------------------------
// Kernel -1: detect nlist element width. Indices are < 50000 < 2^31, so in
// little-endian int64 storage every odd 32-bit word is zero; in int32 storage
// the odd words are random indices. OR the odd words of the first 8 KB
// (in-bounds under either layout: min buffer = 6.4 MB).
// ---------------------------------------------------------------------------
__global__ void detect_nlist_kernel(const unsigned int* __restrict__ nl) {
    const int lane = threadIdx.x;          // one warp
    unsigned int acc = 0;
#pragma unroll
    for (int k = 0; k < 32; k++) {
        // odd word indices: 1, 3, 5, ... (lane-strided)
        acc |= nl[1 + 2 * (lane + 32 * k)];   // max word idx 2047 -> 8KB
    }
#pragma unroll
    for (int o = 16; o > 0; o >>= 1)
        acc |= __shfl_xor_sync(0xffffffffu, acc, o);
    if (lane == 0) g_nlist_is64 = (acc == 0u) ? 1 : 0;
}

// ---------------------------------------------------------------------------
// Kernel 0: transpose w (F,F,E) -> Wr (K=1024, 128) with row kk = n*128+l
// ---------------------------------------------------------------------------
__global__ void transpose_w_kernel(const float* __restrict__ w) {
    int idx = blockIdx.x * blockDim.x + threadIdx.x;
    if (idx >= KDIM * FDIM) return;
    int kk = idx >> 7;          // n*128 + l
    int m  = idx & 127;
    int n  = kk >> 7;
    int l  = kk & 127;
    w_r[idx] = w[(l * FDIM + m) * EDIM + n];
}

// ---------------------------------------------------------------------------
// Kernel 1: stage 1 — G[i, n*128+l] = sum_j edges[i,j,n] * nodes[nlist[i,j], l]
// One warp per node i. Lane owns l = lane*4..lane*4+3 (float4).
// ---------------------------------------------------------------------------
__device__ __forceinline__ void fma4(float4& a, float s, const float4& x) {
    a.x = fmaf(s, x.x, a.x);
    a.y = fmaf(s, x.y, a.y);
    a.z = fmaf(s, x.z, a.z);
    a.w = fmaf(s, x.w, a.w);
}

__global__ void __launch_bounds__(256) stage1_kernel(
    const float* __restrict__ nodes,
    const void* __restrict__ nlist,
    const float* __restrict__ edges)
{
    __shared__ int   s_nb[8][KNBR];
    __shared__ float s_e[8][KNBR * EDIM];   // [j*8 + n]

    const int warp = threadIdx.x >> 5;
    const int lane = threadIdx.x & 31;
    const int i = blockIdx.x * 8 + warp;    // grid = 6250 -> exactly 50000 nodes

    // neighbor index, dtype-agnostic load + defensive clamp
    const size_t nidx = (size_t)i * KNBR + lane;
    int nbi;
    if (g_nlist_is64) {
        nbi = (int)((const long long*)nlist)[nidx];
    } else {
        nbi = ((const int*)nlist)[nidx];
    }
    nbi = nbi < 0 ? 0 : (nbi >= N_NODES ? N_NODES - 1 : nbi);
    s_nb[warp][lane] = nbi;

    // edges row: 256 contiguous floats
    const float4* e4 = (const float4*)(edges + (size_t)i * (KNBR * EDIM));
    float4* se4 = (float4*)s_e[warp];
    se4[lane * 2 + 0] = e4[lane * 2 + 0];
    se4[lane * 2 + 1] = e4[lane * 2 + 1];
    __syncwarp();

    float4 acc[EDIM];
#pragma unroll
    for (int n = 0; n < EDIM; n++) acc[n] = make_float4(0.f, 0.f, 0.f, 0.f);

#pragma unroll 4
    for (int j = 0; j < KNBR; j++) {
        const int nb = s_nb[warp][j];
        const float4 x = *(const float4*)(nodes + (size_t)nb * FDIM + lane * 4);
        const float4 e0 = *(const float4*)&s_e[warp][j * 8 + 0];
        const float4 e1 = *(const float4*)&s_e[warp][j * 8 + 4];
        fma4(acc[0], e0.x, x);
        fma4(acc[1], e0.y, x);
        fma4(acc[2], e0.z, x);
        fma4(acc[3], e0.w, x);
        fma4(acc[4], e1.x, x);
        fma4(acc[5], e1.y, x);
        fma4(acc[6], e1.z, x);
        fma4(acc[7], e1.w, x);
    }

    float* gp = g_scratch + (size_t)i * KDIM;
#pragma unroll
    for (int n = 0; n < EDIM; n++) {
        *(float4*)(gp + n * FDIM + lane * 4) = acc[n];
    }
}

// ---------------------------------------------------------------------------
// Kernel 2: stage 2 — out[i,m] = inv_degree[i] * sum_kk G[i,kk] * Wr[kk,m]
// Classic SGEMM: BM=128, BN=128, BK=16, 256 threads, 8x8 microtile,
// double-buffered smem, float4 everywhere. M=50000 (last CTA partial-store).
// ---------------------------------------------------------------------------
__global__ void __launch_bounds__(256, 2) stage2_kernel(
    const float* __restrict__ inv_degree,
    float* __restrict__ out)
{
    __shared__ float As[2][16][132];   // padded to 132 (16B aligned, conflict-free)
    __shared__ float Bs[2][16][128];

    const int tid = threadIdx.x;
    const int m0  = blockIdx.x * 128;

    const int tx = tid & 15;           // output col group  (tx*8 .. tx*8+7)
    const int ty = tid >> 4;           // output row group  (ty*8 .. ty*8+7)

    const int a_row = tid >> 2;        // 0..63
    const int a_col = (tid & 3) << 2;  // 0,4,8,12
    const int b_row = tid >> 5;        // 0..7
    const int b_col = (tid & 31) << 2; // 0..124

    const float* Ag = g_scratch + (size_t)(m0 + a_row) * KDIM + a_col;
    const float* Bg = w_r + b_row * FDIM + b_col;

    float acc[8][8];
#pragma unroll
    for (int r = 0; r < 8; r++)
#pragma unroll
        for (int c = 0; c < 8; c++) acc[r][c] = 0.f;

    float4 na0, na1, nb0, nb1;

    // prologue: tile 0 -> buffer 0
    na0 = *(const float4*)(Ag);
    na1 = *(const float4*)(Ag + (size_t)64 * KDIM);
    nb0 = *(const float4*)(Bg);
    nb1 = *(const float4*)(Bg + 8 * FDIM);
    As[0][a_col + 0][a_row]      = na0.x;
    As[0][a_col + 1][a_row]      = na0.y;
    As[0][a_col + 2][a_row]      = na0.z;
    As[0][a_col + 3][a_row]      = na0.w;
    As[0][a_col + 0][a_row + 64] = na1.x;
    As[0][a_col + 1][a_row + 64] = na1.y;
    As[0][a_col + 2][a_row + 64] = na1.z;
    As[0][a_col + 3][a_row + 64] = na1.w;
    *(float4*)&Bs[0][b_row][b_col]     = nb0;
    *(float4*)&Bs[0][b_row + 8][b_col] = nb1;
    __syncthreads();

#pragma unroll 1
    for (int kt = 0; kt < 64; kt++) {
        const int buf = kt & 1;

        if (kt < 63) {
            const float* Agn = Ag + (kt + 1) * 16;
            const float* Bgn = Bg + (size_t)(kt + 1) * 16 * FDIM;
            na0 = *(const float4*)(Agn);
            na1 = *(const float4*)(Agn + (size_t)64 * KDIM);
            nb0 = *(const float4*)(Bgn);
            nb1 = *(const float4*)(Bgn + 8 * FDIM);
        }

#pragma unroll
        for (int k = 0; k < 16; k++) {
            const float4 a0 = *(const float4*)&As[buf][k][ty * 8];
            const float4 a1 = *(const float4*)&As[buf][k][ty * 8 + 4];
            const float4 b0 = *(const float4*)&Bs[buf][k][tx * 8];
            const float4 b1 = *(const float4*)&Bs[buf][k][tx * 8 + 4];
            const float ar[8] = {a0.x, a0.y, a0.z, a0.w, a1.x, a1.y, a1.z, a1.w};
            const float br[8] = {b0.x, b0.y, b0.z, b0.w, b1.x, b1.y, b1.z, b1.w};
#pragma unroll
            for (int r = 0; r < 8; r++)
#pragma unroll
                for (int c = 0; c < 8; c++)
                    acc[r][c] = fmaf(ar[r], br[c], acc[r][c]);
        }

        if (kt < 63) {
            const int nbuf = buf ^ 1;
            As[nbuf][a_col + 0][a_row]      = na0.x;
            As[nbuf][a_col + 1][a_row]      = na0.y;
            As[nbuf][a_col + 2][a_row]      = na0.z;
            As[nbuf][a_col + 3][a_row]      = na0.w;
            As[nbuf][a_col + 0][a_row + 64] = na1.x;
            As[nbuf][a_col + 1][a_row + 64] = na1.y;
            As[nbuf][a_col + 2][a_row + 64] = na1.z;
            As[nbuf][a_col + 3][a_row + 64] = na1.w;
            *(float4*)&Bs[nbuf][b_row][b_col]     = nb0;
            *(float4*)&Bs[nbuf][b_row + 8][b_col] = nb1;
            __syncthreads();
        }
    }

    // epilogue: scale by inv_degree, guarded store
#pragma unroll
    for (int r = 0; r < 8; r++) {
        const int gi = m0 + ty * 8 + r;
        if (gi < N_NODES) {
            const float s = inv_degree[gi];
            float4 o0, o1;
            o0.x = acc[r][0] * s; o0.y = acc[r][1] * s;
            o0.z = acc[r][2] * s; o0.w = acc[r][3] * s;
            o1.x = acc[r][4] * s; o1.y = acc[r][5] * s;
            o1.z = acc[r][6] * s; o1.w = acc[r][7] * s;
            float* op = out + (size_t)gi * FDIM + tx * 8;
            *(float4*)(op)     = o0;
            *(float4*)(op + 4) = o1;
        }
    }
}

// ---------------------------------------------------------------------------
// Launch. Inputs identified BY ELEMENT COUNT (all five distinct), robust to
// any metadata.txt ordering. nlist may be reported as 1,600,000 (native) or
// 3,200,000 (int64 counted as int32 pairs); its element width is detected at
// runtime on device.
//   nodes      : 6,400,000   (50000*128)  float32
//   nlist      : 1,600,000   (50000*32)   int
//   edges      : 12,800,000  (50000*32*8) float32
//   inv_degree : 50,000                   float32
//   w          : 131,072     (128*128*8)  float32
// ---------------------------------------------------------------------------
extern "C" void kernel_launch(void* const* d_in, const int* in_sizes, int n_in,
                              void* d_out, int out_size) {
    const float* nodes      = nullptr;
    const void*  nlist      = nullptr;
    const float* edges      = nullptr;
    const float* inv_degree = nullptr;
    const float* w          = nullptr;

    for (int i = 0; i < n_in; i++) {
        switch (in_sizes[i]) {
            case 6400000:  nodes      = (const float*)d_in[i]; break;
            case 1600000:  nlist      = d_in[i];               break;
            case 3200000:  nlist      = d_in[i];               break;
            case 12800000: edges      = (const float*)d_in[i]; break;
            case 50000:    inv_degree = (const float*)d_in[i]; break;
            case 131072:   w          = (const float*)d_in[i]; break;
            default: break;
        }
    }
    if (!nodes || !nlist || !edges || !inv_degree || !w) return;

    float* out = (float*)d_out;

    detect_nlist_kernel<<<1, 32>>>((const unsigned int*)nlist);
    transpose_w_kernel<<<(KDIM * FDIM + 255) / 256, 256>>>(w);
    stage1_kernel<<<N_NODES / 8, 256>>>(nodes, nlist, edges);
    stage2_kernel<<<(N_NODES + 127) / 128, 256>>>(inv_degree, out);
}

// round 5
// speedup vs baseline: 1.7910x; 1.7910x over previous
#include <cuda_runtime.h>
#include <cuda_bf16.h>
#include <cstdint>
#include <cstddef>

// Problem constants
#define N_NODES 50000
#define N_PAD   50048
#define KNBR    32
#define FDIM    128
#define EDIM    8
#define KDIM    1024          // FDIM * EDIM

// G split into bf16 hi/lo, rows [i][kk], kk = n*128 + l
__device__ __nv_bfloat16 g_hi[(size_t)N_PAD * KDIM];   // 102.5 MB
__device__ __nv_bfloat16 g_lo[(size_t)N_PAD * KDIM];   // 102.5 MB
// W rearranged to [kk][m] bf16 hi/lo
__device__ __nv_bfloat16 wt_hi[KDIM * FDIM];
__device__ __nv_bfloat16 wt_lo[KDIM * FDIM];
// nlist dtype flag: 1 = int64 storage, 0 = int32 storage
__device__ int g_nlist_is64;

// ---------------------------------------------------------------------------
// helpers
// ---------------------------------------------------------------------------
__device__ __forceinline__ uint32_t smem_u32(const void* p) {
    uint32_t a;
    asm("{ .reg .u64 t; cvta.to.shared.u64 t, %1; cvt.u32.u64 %0, t; }" : "=r"(a) : "l"(p));
    return a;
}

__device__ __forceinline__ void cp_async16(uint32_t dst, const void* src) {
    asm volatile("cp.async.cg.shared.global [%0], [%1], 16;" :: "r"(dst), "l"(src));
}
__device__ __forceinline__ void cp_commit() {
    asm volatile("cp.async.commit_group;");
}

__device__ __forceinline__ void ldm_x4(uint32_t* r, uint32_t addr) {
    asm volatile("ldmatrix.sync.aligned.m8n8.x4.shared.b16 {%0,%1,%2,%3}, [%4];"
                 : "=r"(r[0]), "=r"(r[1]), "=r"(r[2]), "=r"(r[3]) : "r"(addr));
}
__device__ __forceinline__ void ldm_x4t(uint32_t* r, uint32_t addr) {
    asm volatile("ldmatrix.sync.aligned.m8n8.x4.trans.shared.b16 {%0,%1,%2,%3}, [%4];"
                 : "=r"(r[0]), "=r"(r[1]), "=r"(r[2]), "=r"(r[3]) : "r"(addr));
}

__device__ __forceinline__ void mma_bf16(float* c, const uint32_t* a, const uint32_t* b) {
    asm volatile(
        "mma.sync.aligned.m16n8k16.row.col.f32.bf16.bf16.f32 "
        "{%0,%1,%2,%3}, {%4,%5,%6,%7}, {%8,%9}, {%0,%1,%2,%3};"
        : "+f"(c[0]), "+f"(c[1]), "+f"(c[2]), "+f"(c[3])
        : "r"(a[0]), "r"(a[1]), "r"(a[2]), "r"(a[3]), "r"(b[0]), "r"(b[1]));
}

// ---------------------------------------------------------------------------
// Kernel -1: detect nlist element width (odd 32-bit words all-zero => int64)
// ---------------------------------------------------------------------------
__global__ void detect_nlist_kernel(const unsigned int* __restrict__ nl) {
    const int lane = threadIdx.x;
    unsigned int acc = 0;
#pragma unroll
    for (int k = 0; k < 32; k++)
        acc |= nl[1 + 2 * (lane + 32 * k)];
#pragma unroll
    for (int o = 16; o > 0; o >>= 1)
        acc |= __shfl_xor_sync(0xffffffffu, acc, o);
    if (lane == 0) g_nlist_is64 = (acc == 0u) ? 1 : 0;
}

// ---------------------------------------------------------------------------
// Kernel 0: w (F,F,E) -> wt_hi/wt_lo [kk][m],  kk = n*128 + l
// ---------------------------------------------------------------------------
__global__ void transpose_w_kernel(const float* __restrict__ w) {
    int idx = blockIdx.x * blockDim.x + threadIdx.x;
    if (idx >= KDIM * FDIM) return;
    int kk = idx >> 7;          // n*128 + l
    int m  = idx & 127;
    int n  = kk >> 7;
    int l  = kk & 127;
    float v = w[(l * FDIM + m) * EDIM + n];
    __nv_bfloat16 hi = __float2bfloat16_rn(v);
    __nv_bfloat16 lo = __float2bfloat16_rn(v - __bfloat162float(hi));
    wt_hi[idx] = hi;
    wt_lo[idx] = lo;
}

// ---------------------------------------------------------------------------
// Kernel 1: stage 1 — G row, written as bf16 hi/lo split
// One warp per node i. Lane owns l = lane*4..lane*4+3.
// ---------------------------------------------------------------------------
__device__ __forceinline__ void fma4(float4& a, float s, const float4& x) {
    a.x = fmaf(s, x.x, a.x);
    a.y = fmaf(s, x.y, a.y);
    a.z = fmaf(s, x.z, a.z);
    a.w = fmaf(s, x.w, a.w);
}

__global__ void __launch_bounds__(256) stage1_kernel(
    const float* __restrict__ nodes,
    const void* __restrict__ nlist,
    const float* __restrict__ edges)
{
    __shared__ int   s_nb[8][KNBR];
    __shared__ float s_e[8][KNBR * EDIM];

    const int warp = threadIdx.x >> 5;
    const int lane = threadIdx.x & 31;
    const int i = blockIdx.x * 8 + warp;

    const size_t nidx = (size_t)i * KNBR + lane;
    int nbi;
    if (g_nlist_is64) nbi = (int)((const long long*)nlist)[nidx];
    else              nbi = ((const int*)nlist)[nidx];
    nbi = nbi < 0 ? 0 : (nbi >= N_NODES ? N_NODES - 1 : nbi);
    s_nb[warp][lane] = nbi;

    const float4* e4 = (const float4*)(edges + (size_t)i * (KNBR * EDIM));
    float4* se4 = (float4*)s_e[warp];
    se4[lane * 2 + 0] = e4[lane * 2 + 0];
    se4[lane * 2 + 1] = e4[lane * 2 + 1];
    __syncwarp();

    float4 acc[EDIM];
#pragma unroll
    for (int n = 0; n < EDIM; n++) acc[n] = make_float4(0.f, 0.f, 0.f, 0.f);

#pragma unroll 4
    for (int j = 0; j < KNBR; j++) {
        const int nb = s_nb[warp][j];
        const float4 x = *(const float4*)(nodes + (size_t)nb * FDIM + lane * 4);
        const float4 e0 = *(const float4*)&s_e[warp][j * 8 + 0];
        const float4 e1 = *(const float4*)&s_e[warp][j * 8 + 4];
        fma4(acc[0], e0.x, x);
        fma4(acc[1], e0.y, x);
        fma4(acc[2], e0.z, x);
        fma4(acc[3], e0.w, x);
        fma4(acc[4], e1.x, x);
        fma4(acc[5], e1.y, x);
        fma4(acc[6], e1.z, x);
        fma4(acc[7], e1.w, x);
    }

    const size_t rbase = (size_t)i * KDIM + lane * 4;
#pragma unroll
    for (int n = 0; n < EDIM; n++) {
        float v0 = acc[n].x, v1 = acc[n].y, v2 = acc[n].z, v3 = acc[n].w;
        __nv_bfloat16 h0 = __float2bfloat16_rn(v0);
        __nv_bfloat16 h1 = __float2bfloat16_rn(v1);
        __nv_bfloat16 h2 = __float2bfloat16_rn(v2);
        __nv_bfloat16 h3 = __float2bfloat16_rn(v3);
        __nv_bfloat16 l0 = __float2bfloat16_rn(v0 - __bfloat162float(h0));
        __nv_bfloat16 l1 = __float2bfloat16_rn(v1 - __bfloat162float(h1));
        __nv_bfloat16 l2 = __float2bfloat16_rn(v2 - __bfloat162float(h2));
        __nv_bfloat16 l3 = __float2bfloat16_rn(v3 - __bfloat162float(h3));
        __nv_bfloat162 hA = __nv_bfloat162(h0, h1), hB = __nv_bfloat162(h2, h3);
        __nv_bfloat162 lA = __nv_bfloat162(l0, l1), lB = __nv_bfloat162(l2, l3);
        *(uint2*)&g_hi[rbase + n * FDIM] = make_uint2(*(uint32_t*)&hA, *(uint32_t*)&hB);
        *(uint2*)&g_lo[rbase + n * FDIM] = make_uint2(*(uint32_t*)&lA, *(uint32_t*)&lB);
    }
}

// ---------------------------------------------------------------------------
// Kernel 2: mma.sync bf16 split GEMM.
//   out[i,m] = inv_degree[i] * sum_kk (Ghi+Glo)[i,kk] * (Whi+Wlo)[kk,m]
//   with the lo*lo term dropped.
// CTA tile 128x128, K-chunks of 32, cp.async double buffer, 8 warps (4m x 2n),
// warp tile 32x64, m16n8k16 fragments via ldmatrix.
// Smem swizzles:
//   A tile [128][32] bf16 (64B rows, 4 chunks):  chunk' = c ^ ((row>>1)&3)
//   B tile [32][128] bf16 (256B rows, 16 chunks): chunk' = c ^ (row&15)
// ---------------------------------------------------------------------------
#define KC        32
#define NKCHUNKS  (KDIM / KC)         // 32
#define A_BYTES   8192                // 128*32*2
#define B_BYTES   8192                // 32*128*2
#define BUF_BYTES 32768               // Ahi|Alo|Bhi|Blo
#define OFF_AHI   0
#define OFF_ALO   8192
#define OFF_BHI   16384
#define OFF_BLO   24576
#define SMEM_DYN  (2 * BUF_BYTES)

__global__ void __launch_bounds__(256) stage2_mma_kernel(
    const float* __restrict__ inv_degree,
    float* __restrict__ out)
{
    extern __shared__ __align__(128) char smem[];
    const uint32_t sbase = smem_u32(smem);

    const int tid    = threadIdx.x;
    const int lane   = tid & 31;
    const int wid    = tid >> 5;
    const int warp_m = wid & 3;        // 0..3 -> m offset 32*warp_m
    const int warp_n = wid >> 2;       // 0..1 -> n offset 64*warp_n
    const int m0     = blockIdx.x * 128;

    float acc[2][8][4];
#pragma unroll
    for (int mt = 0; mt < 2; mt++)
#pragma unroll
        for (int nt = 0; nt < 8; nt++)
#pragma unroll
            for (int q = 0; q < 4; q++) acc[mt][nt][q] = 0.f;

    // ---- async load of one K-chunk into buffer b ----
    auto load_chunk = [&](int kc, int b) {
        const uint32_t sb = sbase + b * BUF_BYTES;
        // A: 512 16B chunks per dtype
#pragma unroll
        for (int it = 0; it < 2; it++) {
            const int ca  = tid + it * 256;
            const int row = ca >> 2;
            const int c   = ca & 3;
            const uint32_t so = row * 64 + ((c ^ ((row >> 1) & 3)) << 4);
            const size_t ge = (size_t)(m0 + row) * KDIM + kc * KC + c * 8;
            cp_async16(sb + OFF_AHI + so, g_hi + ge);
            cp_async16(sb + OFF_ALO + so, g_lo + ge);
        }
        // B: 512 16B chunks per dtype
#pragma unroll
        for (int it = 0; it < 2; it++) {
            const int cb  = tid + it * 256;
            const int row = cb >> 4;
            const int c   = cb & 15;
            const uint32_t so = row * 256 + ((c ^ (row & 15)) << 4);
            const size_t ge = (size_t)(kc * KC + row) * FDIM + c * 8;
            cp_async16(sb + OFF_BHI + so, wt_hi + ge);
            cp_async16(sb + OFF_BLO + so, wt_lo + ge);
        }
        cp_commit();
    };

    load_chunk(0, 0);

#pragma unroll 1
    for (int kc = 0; kc < NKCHUNKS; kc++) {
        if (kc < NKCHUNKS - 1) load_chunk(kc + 1, (kc + 1) & 1);

        if (kc < NKCHUNKS - 1) asm volatile("cp.async.wait_group 1;");
        else                   asm volatile("cp.async.wait_group 0;");
        __syncthreads();

        const uint32_t sb = sbase + (kc & 1) * BUF_BYTES;

#pragma unroll
        for (int k16 = 0; k16 < 2; k16++) {
            // A fragments (2 m16 tiles, hi+lo)
            uint32_t ahi[2][4], alo[2][4];
            const int rA   = (lane & 7) + ((lane >> 3) & 1) * 8;
            const int kch  = k16 * 2 + (lane >> 4);
#pragma unroll
            for (int mt = 0; mt < 2; mt++) {
                const int row = warp_m * 32 + mt * 16 + rA;
                const uint32_t off = row * 64 + ((kch ^ ((row >> 1) & 3)) << 4);
                ldm_x4(ahi[mt], sb + OFF_AHI + off);
                ldm_x4(alo[mt], sb + OFF_ALO + off);
            }
            // B fragments, 4 n16 groups, each = 2 n8 frags; mma immediately
            const int rB = k16 * 16 + (lane & 7) + ((lane >> 3) & 1) * 8;
#pragma unroll
            for (int nt16 = 0; nt16 < 4; nt16++) {
                const int nch = warp_n * 8 + nt16 * 2 + (lane >> 4);
                const uint32_t off = rB * 256 + ((nch ^ (rB & 15)) << 4);
                uint32_t bhi[4], blo[4];
                ldm_x4t(bhi, sb + OFF_BHI + off);
                ldm_x4t(blo, sb + OFF_BLO + off);
#pragma unroll
                for (int mt = 0; mt < 2; mt++) {
                    mma_bf16(acc[mt][nt16 * 2 + 0], ahi[mt], bhi + 0);
                    mma_bf16(acc[mt][nt16 * 2 + 1], ahi[mt], bhi + 2);
                    mma_bf16(acc[mt][nt16 * 2 + 0], ahi[mt], blo + 0);
                    mma_bf16(acc[mt][nt16 * 2 + 1], ahi[mt], blo + 2);
                    mma_bf16(acc[mt][nt16 * 2 + 0], alo[mt], bhi + 0);
                    mma_bf16(acc[mt][nt16 * 2 + 1], alo[mt], bhi + 2);
                }
            }
        }
        __syncthreads();
    }

    // ---- epilogue: scale + store ----
#pragma unroll
    for (int mt = 0; mt < 2; mt++) {
        const int r0 = m0 + warp_m * 32 + mt * 16 + (lane >> 2);
        const int r1 = r0 + 8;
        const float s0 = (r0 < N_NODES) ? inv_degree[r0] : 0.f;
        const float s1 = (r1 < N_NODES) ? inv_degree[r1] : 0.f;
#pragma unroll
        for (int nt = 0; nt < 8; nt++) {
            const int col = warp_n * 64 + nt * 8 + (lane & 3) * 2;
            if (r0 < N_NODES) {
                float2 o = make_float2(acc[mt][nt][0] * s0, acc[mt][nt][1] * s0);
                *(float2*)(out + (size_t)r0 * FDIM + col) = o;
            }
            if (r1 < N_NODES) {
                float2 o = make_float2(acc[mt][nt][2] * s1, acc[mt][nt][3] * s1);
                *(float2*)(out + (size_t)r1 * FDIM + col) = o;
            }
        }
    }
}

// ---------------------------------------------------------------------------
// Launch. Inputs identified BY ELEMENT COUNT (all five distinct).
// ---------------------------------------------------------------------------
extern "C" void kernel_launch(void* const* d_in, const int* in_sizes, int n_in,
                              void* d_out, int out_size) {
    const float* nodes      = nullptr;
    const void*  nlist      = nullptr;
    const float* edges      = nullptr;
    const float* inv_degree = nullptr;
    const float* w          = nullptr;

    for (int i = 0; i < n_in; i++) {
        switch (in_sizes[i]) {
            case 6400000:  nodes      = (const float*)d_in[i]; break;
            case 1600000:  nlist      = d_in[i];               break;
            case 3200000:  nlist      = d_in[i];               break;
            case 12800000: edges      = (const float*)d_in[i]; break;
            case 50000:    inv_degree = (const float*)d_in[i]; break;
            case 131072:   w          = (const float*)d_in[i]; break;
            default: break;
        }
    }
    if (!nodes || !nlist || !edges || !inv_degree || !w) return;

    float* out = (float*)d_out;

    cudaFuncSetAttribute(stage2_mma_kernel,
                         cudaFuncAttributeMaxDynamicSharedMemorySize, SMEM_DYN);

    detect_nlist_kernel<<<1, 32>>>((const unsigned int*)nlist);
    transpose_w_kernel<<<(KDIM * FDIM + 255) / 256, 256>>>(w);
    stage1_kernel<<<N_NODES / 8, 256>>>(nodes, nlist, edges);
    stage2_mma_kernel<<<(N_NODES + 127) / 128, 256, SMEM_DYN>>>(inv_degree, out);
}

// round 6
// speedup vs baseline: 2.0051x; 1.1195x over previous
#include <cuda_runtime.h>
#include <cuda_bf16.h>
#include <cstdint>
#include <cstddef>

// Problem constants
#define N_NODES 50000
#define N_PAD   50048
#define KNBR    32
#define FDIM    128
#define EDIM    8
#define KDIM    1024          // FDIM * EDIM

// G split into bf16 hi/lo, rows [i][kk], kk = n*128 + l
__device__ __nv_bfloat16 g_hi[(size_t)N_PAD * KDIM];   // 102.5 MB
__device__ __nv_bfloat16 g_lo[(size_t)N_PAD * KDIM];   // 102.5 MB
// W rearranged to [kk][m] bf16 hi/lo
__device__ __nv_bfloat16 wt_hi[KDIM * FDIM];
__device__ __nv_bfloat16 wt_lo[KDIM * FDIM];
// nlist dtype flag: 1 = int64 storage, 0 = int32 storage
__device__ int g_nlist_is64;

// ---------------------------------------------------------------------------
// helpers
// ---------------------------------------------------------------------------
__device__ __forceinline__ uint32_t smem_u32(const void* p) {
    uint32_t a;
    asm("{ .reg .u64 t; cvta.to.shared.u64 t, %1; cvt.u32.u64 %0, t; }" : "=r"(a) : "l"(p));
    return a;
}

__device__ __forceinline__ void cp_async16(uint32_t dst, const void* src) {
    asm volatile("cp.async.cg.shared.global [%0], [%1], 16;" :: "r"(dst), "l"(src));
}
__device__ __forceinline__ void cp_commit() {
    asm volatile("cp.async.commit_group;");
}

__device__ __forceinline__ void ldm_x4(uint32_t* r, uint32_t addr) {
    asm volatile("ldmatrix.sync.aligned.m8n8.x4.shared.b16 {%0,%1,%2,%3}, [%4];"
                 : "=r"(r[0]), "=r"(r[1]), "=r"(r[2]), "=r"(r[3]) : "r"(addr));
}
__device__ __forceinline__ void ldm_x4t(uint32_t* r, uint32_t addr) {
    asm volatile("ldmatrix.sync.aligned.m8n8.x4.trans.shared.b16 {%0,%1,%2,%3}, [%4];"
                 : "=r"(r[0]), "=r"(r[1]), "=r"(r[2]), "=r"(r[3]) : "r"(addr));
}

__device__ __forceinline__ void mma_bf16(float* c, const uint32_t* a, const uint32_t* b) {
    asm volatile(
        "mma.sync.aligned.m16n8k16.row.col.f32.bf16.bf16.f32 "
        "{%0,%1,%2,%3}, {%4,%5,%6,%7}, {%8,%9}, {%0,%1,%2,%3};"
        : "+f"(c[0]), "+f"(c[1]), "+f"(c[2]), "+f"(c[3])
        : "r"(a[0]), "r"(a[1]), "r"(a[2]), "r"(a[3]), "r"(b[0]), "r"(b[1]));
}

// ---------------------------------------------------------------------------
// Kernel -1: detect nlist element width (odd 32-bit words all-zero => int64)
// ---------------------------------------------------------------------------
__global__ void detect_nlist_kernel(const unsigned int* __restrict__ nl) {
    const int lane = threadIdx.x;
    unsigned int acc = 0;
#pragma unroll
    for (int k = 0; k < 32; k++)
        acc |= nl[1 + 2 * (lane + 32 * k)];
#pragma unroll
    for (int o = 16; o > 0; o >>= 1)
        acc |= __shfl_xor_sync(0xffffffffu, acc, o);
    if (lane == 0) g_nlist_is64 = (acc == 0u) ? 1 : 0;
}

// ---------------------------------------------------------------------------
// Kernel 0: w (F,F,E) -> wt_hi/wt_lo [kk][m],  kk = n*128 + l
// ---------------------------------------------------------------------------
__global__ void transpose_w_kernel(const float* __restrict__ w) {
    int idx = blockIdx.x * blockDim.x + threadIdx.x;
    if (idx >= KDIM * FDIM) return;
    int kk = idx >> 7;          // n*128 + l
    int m  = idx & 127;
    int n  = kk >> 7;
    int l  = kk & 127;
    float v = w[(l * FDIM + m) * EDIM + n];
    __nv_bfloat16 hi = __float2bfloat16_rn(v);
    __nv_bfloat16 lo = __float2bfloat16_rn(v - __bfloat162float(hi));
    wt_hi[idx] = hi;
    wt_lo[idx] = lo;
}

// ---------------------------------------------------------------------------
// Kernel 1: stage 1 — G row, written as bf16 hi/lo split
// One warp per node i. Lane owns l = lane*4..lane*4+3.
// ---------------------------------------------------------------------------
__device__ __forceinline__ void fma4(float4& a, float s, const float4& x) {
    a.x = fmaf(s, x.x, a.x);
    a.y = fmaf(s, x.y, a.y);
    a.z = fmaf(s, x.z, a.z);
    a.w = fmaf(s, x.w, a.w);
}

__global__ void __launch_bounds__(256) stage1_kernel(
    const float* __restrict__ nodes,
    const void* __restrict__ nlist,
    const float* __restrict__ edges)
{
    __shared__ int   s_nb[8][KNBR];
    __shared__ float s_e[8][KNBR * EDIM];

    const int warp = threadIdx.x >> 5;
    const int lane = threadIdx.x & 31;
    const int i = blockIdx.x * 8 + warp;

    const size_t nidx = (size_t)i * KNBR + lane;
    int nbi;
    if (g_nlist_is64) nbi = (int)((const long long*)nlist)[nidx];
    else              nbi = ((const int*)nlist)[nidx];
    nbi = nbi < 0 ? 0 : (nbi >= N_NODES ? N_NODES - 1 : nbi);
    s_nb[warp][lane] = nbi;

    const float4* e4 = (const float4*)(edges + (size_t)i * (KNBR * EDIM));
    float4* se4 = (float4*)s_e[warp];
    se4[lane * 2 + 0] = e4[lane * 2 + 0];
    se4[lane * 2 + 1] = e4[lane * 2 + 1];
    __syncwarp();

    float4 acc[EDIM];
#pragma unroll
    for (int n = 0; n < EDIM; n++) acc[n] = make_float4(0.f, 0.f, 0.f, 0.f);

#pragma unroll 4
    for (int j = 0; j < KNBR; j++) {
        const int nb = s_nb[warp][j];
        const float4 x = *(const float4*)(nodes + (size_t)nb * FDIM + lane * 4);
        const float4 e0 = *(const float4*)&s_e[warp][j * 8 + 0];
        const float4 e1 = *(const float4*)&s_e[warp][j * 8 + 4];
        fma4(acc[0], e0.x, x);
        fma4(acc[1], e0.y, x);
        fma4(acc[2], e0.z, x);
        fma4(acc[3], e0.w, x);
        fma4(acc[4], e1.x, x);
        fma4(acc[5], e1.y, x);
        fma4(acc[6], e1.z, x);
        fma4(acc[7], e1.w, x);
    }

    const size_t rbase = (size_t)i * KDIM + lane * 4;
#pragma unroll
    for (int n = 0; n < EDIM; n++) {
        float v0 = acc[n].x, v1 = acc[n].y, v2 = acc[n].z, v3 = acc[n].w;
        __nv_bfloat16 h0 = __float2bfloat16_rn(v0);
        __nv_bfloat16 h1 = __float2bfloat16_rn(v1);
        __nv_bfloat16 h2 = __float2bfloat16_rn(v2);
        __nv_bfloat16 h3 = __float2bfloat16_rn(v3);
        __nv_bfloat16 l0 = __float2bfloat16_rn(v0 - __bfloat162float(h0));
        __nv_bfloat16 l1 = __float2bfloat16_rn(v1 - __bfloat162float(h1));
        __nv_bfloat16 l2 = __float2bfloat16_rn(v2 - __bfloat162float(h2));
        __nv_bfloat16 l3 = __float2bfloat16_rn(v3 - __bfloat162float(h3));
        __nv_bfloat162 hA = __nv_bfloat162(h0, h1), hB = __nv_bfloat162(h2, h3);
        __nv_bfloat162 lA = __nv_bfloat162(l0, l1), lB = __nv_bfloat162(l2, l3);
        *(uint2*)&g_hi[rbase + n * FDIM] = make_uint2(*(uint32_t*)&hA, *(uint32_t*)&hB);
        *(uint2*)&g_lo[rbase + n * FDIM] = make_uint2(*(uint32_t*)&lA, *(uint32_t*)&lB);
    }
}

// ---------------------------------------------------------------------------
// Kernel 2: mma.sync bf16 split GEMM, 3-stage cp.async pipeline, 2 CTAs/SM.
//   out[i,m] = inv_degree[i] * sum_kk (Ghi+Glo)[i,kk] * (Whi+Wlo)[kk,m]
//   (lo*lo term dropped)
// CTA tile 128x128, K-chunks of 32, 8 warps (4m x 2n), warp tile 32x64.
// Smem swizzles:
//   A tile [128][32] bf16 (64B rows, 4 chunks):  chunk' = c ^ ((row>>1)&3)
//   B tile [32][128] bf16 (256B rows, 16 chunks): chunk' = c ^ (row&15)
// ---------------------------------------------------------------------------
#define KC        32
#define NKCHUNKS  (KDIM / KC)         // 32
#define BUF_BYTES 32768               // Ahi|Alo|Bhi|Blo
#define OFF_AHI   0
#define OFF_ALO   8192
#define OFF_BHI   16384
#define OFF_BLO   24576
#define NSTAGES   3
#define SMEM_DYN  (NSTAGES * BUF_BYTES)

__global__ void __launch_bounds__(256, 2) stage2_mma_kernel(
    const float* __restrict__ inv_degree,
    float* __restrict__ out)
{
    extern __shared__ __align__(128) char smem[];
    const uint32_t sbase = smem_u32(smem);

    const int tid    = threadIdx.x;
    const int lane   = tid & 31;
    const int wid    = tid >> 5;
    const int warp_m = wid & 3;        // 0..3 -> m offset 32*warp_m
    const int warp_n = wid >> 2;       // 0..1 -> n offset 64*warp_n
    const int m0     = blockIdx.x * 128;

    float acc[2][8][4];
#pragma unroll
    for (int mt = 0; mt < 2; mt++)
#pragma unroll
        for (int nt = 0; nt < 8; nt++)
#pragma unroll
            for (int q = 0; q < 4; q++) acc[mt][nt][q] = 0.f;

    // ---- async load of one K-chunk into stage buffer b; always commits ----
    auto load_chunk = [&](int kc, int b) {
        if (kc < NKCHUNKS) {
            const uint32_t sb = sbase + b * BUF_BYTES;
#pragma unroll
            for (int it = 0; it < 2; it++) {
                const int ca  = tid + it * 256;
                const int row = ca >> 2;
                const int c   = ca & 3;
                const uint32_t so = row * 64 + ((c ^ ((row >> 1) & 3)) << 4);
                const size_t ge = (size_t)(m0 + row) * KDIM + kc * KC + c * 8;
                cp_async16(sb + OFF_AHI + so, g_hi + ge);
                cp_async16(sb + OFF_ALO + so, g_lo + ge);
            }
#pragma unroll
            for (int it = 0; it < 2; it++) {
                const int cb  = tid + it * 256;
                const int row = cb >> 4;
                const int c   = cb & 15;
                const uint32_t so = row * 256 + ((c ^ (row & 15)) << 4);
                const size_t ge = (size_t)(kc * KC + row) * FDIM + c * 8;
                cp_async16(sb + OFF_BHI + so, wt_hi + ge);
                cp_async16(sb + OFF_BLO + so, wt_lo + ge);
            }
        }
        cp_commit();
    };

    load_chunk(0, 0);
    load_chunk(1, 1);

#pragma unroll 1
    for (int kc = 0; kc < NKCHUNKS; kc++) {
        // chunk kc ready when all but the newest commit have landed
        asm volatile("cp.async.wait_group 1;");
        __syncthreads();   // also: everyone done computing chunk kc-1 (same buffer as kc+2)

        load_chunk(kc + 2, (kc + 2) % NSTAGES);

        const uint32_t sb = sbase + (kc % NSTAGES) * BUF_BYTES;

#pragma unroll
        for (int k16 = 0; k16 < 2; k16++) {
            // A fragments (2 m16 tiles, hi+lo)
            uint32_t ahi[2][4], alo[2][4];
            const int rA   = (lane & 7) + ((lane >> 3) & 1) * 8;
            const int kch  = k16 * 2 + (lane >> 4);
#pragma unroll
            for (int mt = 0; mt < 2; mt++) {
                const int row = warp_m * 32 + mt * 16 + rA;
                const uint32_t off = row * 64 + ((kch ^ ((row >> 1) & 3)) << 4);
                ldm_x4(ahi[mt], sb + OFF_AHI + off);
                ldm_x4(alo[mt], sb + OFF_ALO + off);
            }
            // B fragments, 4 n16 groups, each = 2 n8 frags; mma immediately
            const int rB = k16 * 16 + (lane & 7) + ((lane >> 3) & 1) * 8;
#pragma unroll
            for (int nt16 = 0; nt16 < 4; nt16++) {
                const int nch = warp_n * 8 + nt16 * 2 + (lane >> 4);
                const uint32_t off = rB * 256 + ((nch ^ (rB & 15)) << 4);
                uint32_t bhi[4], blo[4];
                ldm_x4t(bhi, sb + OFF_BHI + off);
                ldm_x4t(blo, sb + OFF_BLO + off);
#pragma unroll
                for (int mt = 0; mt < 2; mt++) {
                    mma_bf16(acc[mt][nt16 * 2 + 0], ahi[mt], bhi + 0);
                    mma_bf16(acc[mt][nt16 * 2 + 1], ahi[mt], bhi + 2);
                    mma_bf16(acc[mt][nt16 * 2 + 0], ahi[mt], blo + 0);
                    mma_bf16(acc[mt][nt16 * 2 + 1], ahi[mt], blo + 2);
                    mma_bf16(acc[mt][nt16 * 2 + 0], alo[mt], bhi + 0);
                    mma_bf16(acc[mt][nt16 * 2 + 1], alo[mt], bhi + 2);
                }
            }
        }
    }

    // ---- epilogue: scale + store ----
#pragma unroll
    for (int mt = 0; mt < 2; mt++) {
        const int r0 = m0 + warp_m * 32 + mt * 16 + (lane >> 2);
        const int r1 = r0 + 8;
        const float s0 = (r0 < N_NODES) ? inv_degree[r0] : 0.f;
        const float s1 = (r1 < N_NODES) ? inv_degree[r1] : 0.f;
#pragma unroll
        for (int nt = 0; nt < 8; nt++) {
            const int col = warp_n * 64 + nt * 8 + (lane & 3) * 2;
            if (r0 < N_NODES) {
                float2 o = make_float2(acc[mt][nt][0] * s0, acc[mt][nt][1] * s0);
                *(float2*)(out + (size_t)r0 * FDIM + col) = o;
            }
            if (r1 < N_NODES) {
                float2 o = make_float2(acc[mt][nt][2] * s1, acc[mt][nt][3] * s1);
                *(float2*)(out + (size_t)r1 * FDIM + col) = o;
            }
        }
    }
}

// ---------------------------------------------------------------------------
// Launch. Inputs identified BY ELEMENT COUNT (all five distinct).
// ---------------------------------------------------------------------------
extern "C" void kernel_launch(void* const* d_in, const int* in_sizes, int n_in,
                              void* d_out, int out_size) {
    const float* nodes      = nullptr;
    const void*  nlist      = nullptr;
    const float* edges      = nullptr;
    const float* inv_degree = nullptr;
    const float* w          = nullptr;

    for (int i = 0; i < n_in; i++) {
        switch (in_sizes[i]) {
            case 6400000:  nodes      = (const float*)d_in[i]; break;
            case 1600000:  nlist      = d_in[i];               break;
            case 3200000:  nlist      = d_in[i];               break;
            case 12800000: edges      = (const float*)d_in[i]; break;
            case 50000:    inv_degree = (const float*)d_in[i]; break;
            case 131072:   w          = (const float*)d_in[i]; break;
            default: break;
        }
    }
    if (!nodes || !nlist || !edges || !inv_degree || !w) return;

    float* out = (float*)d_out;

    cudaFuncSetAttribute(stage2_mma_kernel,
                         cudaFuncAttributeMaxDynamicSharedMemorySize, SMEM_DYN);

    detect_nlist_kernel<<<1, 32>>>((const unsigned int*)nlist);
    transpose_w_kernel<<<(KDIM * FDIM + 255) / 256, 256>>>(w);
    stage1_kernel<<<N_NODES / 8, 256>>>(nodes, nlist, edges);
    stage2_mma_kernel<<<(N_NODES + 127) / 128, 256, SMEM_DYN>>>(inv_degree, out);
}